// round 15
// baseline (speedup 1.0000x reference)
#include <cuda_runtime.h>
#include <cuda_fp16.h>
#include <cstdint>

#define NMAX  100000
#define EMAX  3200000
#define INF   128
#define HID   50
#define PITCH 64
#define SAP   72      // smem row stride in halfs (bank-conflict-free padding)

// ---------------- static device scratch (zero-initialized at load) -----------
__device__ int    g_cursor;        // reset to 0 at tail of k_agg2 each call
__device__ int    g_cnt[NMAX];     // reset to 0 at tail of k_agg2 each call
__device__ int2   g_oc[NMAX];      // (off, cnt)
__device__ int    g_wcur[NMAX];
__device__ int    g_csrc[EMAX];
__device__ float  g_dinv[NMAX];
__device__ __align__(128) __half g_h1h[(size_t)NMAX * PITCH]; // h1' = dinv*(x@W1)
__device__ float2 g_z[NMAX];                                  // z' = dinv*(h@W2)

// ---------------- per-block dtype sniff: int64 edges have zero high words ----
__device__ __forceinline__ int sniff64(const unsigned int* p) {
    unsigned acc = 0;
#pragma unroll
    for (int j = 0; j < 128; j++) acc |= p[2 * j + 1];
    return acc == 0u;        // all-zero odd words -> int64 layout
}

// ---------------- count degrees: int4, REDs are fire-and-forget --------------
__global__ void k_prep(const void* __restrict__ eiv, int E) {
    int is64 = sniff64((const unsigned int*)eiv);
    int i = (blockIdx.x * blockDim.x + threadIdx.x) * 4;
    if (i >= E) return;
    if (!is64 && i + 4 <= E) {
        int4 d = *(const int4*)((const int*)eiv + (size_t)E + i);
        atomicAdd(&g_cnt[d.x], 1);
        atomicAdd(&g_cnt[d.y], 1);
        atomicAdd(&g_cnt[d.z], 1);
        atomicAdd(&g_cnt[d.w], 1);
    } else {
        for (int j = i; j < E && j < i + 4; j++) {
            int d;
            if (is64) d = (int)((const long long*)eiv)[(size_t)E + j];
            else      d = ((const int*)eiv)[(size_t)E + j];
            atomicAdd(&g_cnt[d], 1);
        }
    }
}

// ---------------- region alloc: warp scan + one atomic per warp --------------
__global__ void k_alloc(int N) {
    int i = blockIdx.x * blockDim.x + threadIdx.x;
    int lane = threadIdx.x & 31;
    int c = (i < N) ? g_cnt[i] : 0;
    int x = c;
#pragma unroll
    for (int o = 1; o < 32; o <<= 1) {
        int y = __shfl_up_sync(0xffffffffu, x, o);
        if (lane >= o) x += y;
    }
    int total = __shfl_sync(0xffffffffu, x, 31);
    int base = 0;
    if (lane == 31 && total > 0) base = atomicAdd(&g_cursor, total);
    base = __shfl_sync(0xffffffffu, base, 31);
    if (i < N) {
        int off = base + x - c;
        g_oc[i]   = make_int2(off, c);
        g_wcur[i] = off;
        g_dinv[i] = rsqrtf((float)(c + 1));
    }
}

// ---------------- CSR fill (scalar: value-returning atomics) -----------------
__global__ void k_fill(const void* __restrict__ eiv, int E) {
    int is64 = sniff64((const unsigned int*)eiv);
    int i = blockIdx.x * blockDim.x + threadIdx.x;
    if (i >= E) return;
    int s, d;
    if (is64) {
        const long long* p = (const long long*)eiv;
        s = (int)p[i];
        d = (int)p[(size_t)E + i];
    } else {
        const int* p = (const int*)eiv;
        s = p[i];
        d = p[(size_t)E + i];
    }
    g_csrc[atomicAdd(&g_wcur[d], 1)] = s;
}

// ---------------- GEMM1 via mma.sync m16n8k16: h1' = dinv*(x @ W1) -----------
__global__ void k_gemm1(const float* __restrict__ x, const float* __restrict__ W1, int N) {
    __shared__ __half sA[128 * SAP];
    __shared__ __half sB[64 * SAP];
    int tid  = threadIdx.x;
    int lane = tid & 31;
    int wid  = tid >> 5;
    int node0 = blockIdx.x * 128;
    int r   = lane >> 2;
    int c2i = (lane & 3) * 2;

    float acc[2][8][4];
#pragma unroll
    for (int rg = 0; rg < 2; rg++)
#pragma unroll
        for (int cg = 0; cg < 8; cg++)
#pragma unroll
            for (int q = 0; q < 4; q++) acc[rg][cg][q] = 0.f;

    for (int kh = 0; kh < 2; kh++) {
        for (int idx = tid; idx < 1024; idx += 128) {
            int row = idx >> 3, ch = idx & 7;
            int node = node0 + row;
            float4 f0 = make_float4(0.f, 0.f, 0.f, 0.f), f1 = f0;
            if (node < N) {
                const float* src = x + (size_t)node * INF + kh * 64 + ch * 8;
                f0 = *(const float4*)src;
                f1 = *(const float4*)(src + 4);
            }
            __half2 h0 = __floats2half2_rn(f0.x, f0.y);
            __half2 h1 = __floats2half2_rn(f0.z, f0.w);
            __half2 h2 = __floats2half2_rn(f1.x, f1.y);
            __half2 h3 = __floats2half2_rn(f1.z, f1.w);
            uint4 v;
            v.x = *(uint32_t*)&h0; v.y = *(uint32_t*)&h1;
            v.z = *(uint32_t*)&h2; v.w = *(uint32_t*)&h3;
            *(uint4*)(sA + row * SAP + ch * 8) = v;
        }
        for (int idx = tid; idx < 4096; idx += 128) {
            int n = idx >> 6, k = idx & 63;
            sB[n * SAP + k] = (n < HID) ? __float2half(W1[(kh * 64 + k) * HID + n])
                                        : __half(0.f);
        }
        __syncthreads();
#pragma unroll
        for (int ks = 0; ks < 4; ks++) {
            int k = ks * 16;
            uint32_t b0[8], b1[8];
#pragma unroll
            for (int cg = 0; cg < 8; cg++) {
                const __half* bp = sB + (cg * 8 + r) * SAP + k + c2i;
                b0[cg] = *(const uint32_t*)bp;
                b1[cg] = *(const uint32_t*)(bp + 8);
            }
#pragma unroll
            for (int rg = 0; rg < 2; rg++) {
                const __half* ap = sA + (wid * 32 + rg * 16 + r) * SAP + k + c2i;
                uint32_t a0 = *(const uint32_t*)ap;
                uint32_t a1 = *(const uint32_t*)(ap + 8 * SAP);
                uint32_t a2 = *(const uint32_t*)(ap + 8);
                uint32_t a3 = *(const uint32_t*)(ap + 8 * SAP + 8);
#pragma unroll
                for (int cg = 0; cg < 8; cg++) {
                    asm volatile(
                        "mma.sync.aligned.m16n8k16.row.col.f32.f16.f16.f32 "
                        "{%0,%1,%2,%3}, {%4,%5,%6,%7}, {%8,%9}, {%0,%1,%2,%3};"
                        : "+f"(acc[rg][cg][0]), "+f"(acc[rg][cg][1]),
                          "+f"(acc[rg][cg][2]), "+f"(acc[rg][cg][3])
                        : "r"(a0), "r"(a1), "r"(a2), "r"(a3), "r"(b0[cg]), "r"(b1[cg]));
                }
            }
        }
        __syncthreads();
    }

#pragma unroll
    for (int rg = 0; rg < 2; rg++)
#pragma unroll
        for (int hr = 0; hr < 2; hr++) {
            int node = node0 + wid * 32 + rg * 16 + r + hr * 8;
            if (node < N) {
                float di = g_dinv[node];
                __half* dst = g_h1h + ((size_t)node << 6) + c2i;
#pragma unroll
                for (int cg = 0; cg < 8; cg++) {
                    __half2 hv = __floats2half2_rn(acc[rg][cg][hr * 2] * di,
                                                   acc[rg][cg][hr * 2 + 1] * di);
                    *(__half2*)(dst + cg * 8) = hv;
                }
            }
        }
}

// ---------------- layer-1 agg: 16-lane groups, 8-edge unroll -----------------
__global__ void k_agg1(const float* __restrict__ b1, const float* __restrict__ W2, int N) {
    int gt = blockIdx.x * blockDim.x + threadIdx.x;
    int i = gt >> 4;
    int l = gt & 15;
    if (i >= N) return;
    unsigned gmask = 0xFFFFu << (threadIdx.x & 16);

    float dii = g_dinv[i];
    int2 oc = g_oc[i];
    int beg = oc.x, end = beg + oc.y;

    bool act = l < 13;
    const __half* hbase = g_h1h;
    float a0 = 0.f, a1 = 0.f, a2 = 0.f, a3 = 0.f;
    if (act) {
        uint2 v = *(const uint2*)(hbase + ((size_t)i << 6) + l * 4);
        float2 f0 = __half22float2(*(__half2*)&v.x);
        float2 f1 = __half22float2(*(__half2*)&v.y);
        a0 = f0.x; a1 = f0.y; a2 = f1.x; a3 = f1.y;
    }
    int e = beg;
    int head = (4 - (beg & 3)) & 3;
    for (int j = 0; j < head && e < end; j++, e++) {
        int s = g_csrc[e];
        if (act) {
            uint2 v = *(const uint2*)(hbase + ((size_t)s << 6) + l * 4);
            float2 f0 = __half22float2(*(__half2*)&v.x);
            float2 f1 = __half22float2(*(__half2*)&v.y);
            a0 += f0.x; a1 += f0.y; a2 += f1.x; a3 += f1.y;
        }
    }
    for (; e + 8 <= end; e += 8) {
        int4 qa = *(const int4*)(g_csrc + e);
        int4 qb = *(const int4*)(g_csrc + e + 4);
        if (act) {
            uint2 v0 = *(const uint2*)(hbase + ((size_t)qa.x << 6) + l * 4);
            uint2 v1 = *(const uint2*)(hbase + ((size_t)qa.y << 6) + l * 4);
            uint2 v2 = *(const uint2*)(hbase + ((size_t)qa.z << 6) + l * 4);
            uint2 v3 = *(const uint2*)(hbase + ((size_t)qa.w << 6) + l * 4);
            uint2 v4 = *(const uint2*)(hbase + ((size_t)qb.x << 6) + l * 4);
            uint2 v5 = *(const uint2*)(hbase + ((size_t)qb.y << 6) + l * 4);
            uint2 v6 = *(const uint2*)(hbase + ((size_t)qb.z << 6) + l * 4);
            uint2 v7 = *(const uint2*)(hbase + ((size_t)qb.w << 6) + l * 4);
            float2 p0 = __half22float2(*(__half2*)&v0.x), p1 = __half22float2(*(__half2*)&v0.y);
            float2 p2 = __half22float2(*(__half2*)&v1.x), p3 = __half22float2(*(__half2*)&v1.y);
            float2 p4 = __half22float2(*(__half2*)&v2.x), p5 = __half22float2(*(__half2*)&v2.y);
            float2 p6 = __half22float2(*(__half2*)&v3.x), p7 = __half22float2(*(__half2*)&v3.y);
            float2 p8 = __half22float2(*(__half2*)&v4.x), p9 = __half22float2(*(__half2*)&v4.y);
            float2 pA = __half22float2(*(__half2*)&v5.x), pB = __half22float2(*(__half2*)&v5.y);
            float2 pC = __half22float2(*(__half2*)&v6.x), pD = __half22float2(*(__half2*)&v6.y);
            float2 pE = __half22float2(*(__half2*)&v7.x), pF = __half22float2(*(__half2*)&v7.y);
            a0 += ((p0.x + p2.x) + (p4.x + p6.x)) + ((p8.x + pA.x) + (pC.x + pE.x));
            a1 += ((p0.y + p2.y) + (p4.y + p6.y)) + ((p8.y + pA.y) + (pC.y + pE.y));
            a2 += ((p1.x + p3.x) + (p5.x + p7.x)) + ((p9.x + pB.x) + (pD.x + pF.x));
            a3 += ((p1.y + p3.y) + (p5.y + p7.y)) + ((p9.y + pB.y) + (pD.y + pF.y));
        }
    }
    for (; e + 4 <= end; e += 4) {
        int4 q = *(const int4*)(g_csrc + e);
        if (act) {
            uint2 v0 = *(const uint2*)(hbase + ((size_t)q.x << 6) + l * 4);
            uint2 v1 = *(const uint2*)(hbase + ((size_t)q.y << 6) + l * 4);
            uint2 v2 = *(const uint2*)(hbase + ((size_t)q.z << 6) + l * 4);
            uint2 v3 = *(const uint2*)(hbase + ((size_t)q.w << 6) + l * 4);
            float2 p0 = __half22float2(*(__half2*)&v0.x), p1 = __half22float2(*(__half2*)&v0.y);
            float2 p2 = __half22float2(*(__half2*)&v1.x), p3 = __half22float2(*(__half2*)&v1.y);
            float2 p4 = __half22float2(*(__half2*)&v2.x), p5 = __half22float2(*(__half2*)&v2.y);
            float2 p6 = __half22float2(*(__half2*)&v3.x), p7 = __half22float2(*(__half2*)&v3.y);
            a0 += (p0.x + p2.x) + (p4.x + p6.x);
            a1 += (p0.y + p2.y) + (p4.y + p6.y);
            a2 += (p1.x + p3.x) + (p5.x + p7.x);
            a3 += (p1.y + p3.y) + (p5.y + p7.y);
        }
    }
    for (; e < end; e++) {
        int s = g_csrc[e];
        if (act) {
            uint2 v = *(const uint2*)(hbase + ((size_t)s << 6) + l * 4);
            float2 f0 = __half22float2(*(__half2*)&v.x);
            float2 f1 = __half22float2(*(__half2*)&v.y);
            a0 += f0.x; a1 += f0.y; a2 += f1.x; a3 += f1.y;
        }
    }
    float z0 = 0.f, z1 = 0.f;
    if (l < 12) {
        float4 bb = *(const float4*)(b1 + 4 * l);
        float4 wA = *(const float4*)(W2 + 8 * l);
        float4 wB = *(const float4*)(W2 + 8 * l + 4);
        float h0 = fmaxf(fmaf(a0, dii, bb.x), 0.f);
        float h1 = fmaxf(fmaf(a1, dii, bb.y), 0.f);
        float h2 = fmaxf(fmaf(a2, dii, bb.z), 0.f);
        float h3 = fmaxf(fmaf(a3, dii, bb.w), 0.f);
        z0 = h0 * wA.x + h1 * wA.z + h2 * wB.x + h3 * wB.z;
        z1 = h0 * wA.y + h1 * wA.w + h2 * wB.y + h3 * wB.w;
    } else if (l == 12) {
        float2 bb = *(const float2*)(b1 + 48);
        float4 wA = *(const float4*)(W2 + 96);
        float h0 = fmaxf(fmaf(a0, dii, bb.x), 0.f);
        float h1 = fmaxf(fmaf(a1, dii, bb.y), 0.f);
        z0 = h0 * wA.x + h1 * wA.z;
        z1 = h0 * wA.y + h1 * wA.w;
    }
#pragma unroll
    for (int o = 8; o; o >>= 1) {
        z0 += __shfl_xor_sync(gmask, z0, o, 16);
        z1 += __shfl_xor_sync(gmask, z1, o, 16);
    }
    if (l == 0) g_z[i] = make_float2(z0 * dii, z1 * dii);
}

// ---------------- layer-2 agg + log_softmax (16-lane groups) -----------------
__global__ void k_agg2(const float* __restrict__ b2, float* __restrict__ out, int N) {
    int gt = blockIdx.x * blockDim.x + threadIdx.x;
    int i = gt >> 4, l = gt & 15;
    if (gt == 0) g_cursor = 0;
    if (i >= N) return;
    unsigned gmask = 0xFFFFu << (threadIdx.x & 16);

    int2 oc = g_oc[i];
    int beg = oc.x;
    int end = beg + oc.y;
    float a0 = 0.f, a1 = 0.f;
    for (int e = beg + l; e < end; e += 16) {
        float2 zv = g_z[g_csrc[e]];
        a0 += zv.x;
        a1 += zv.y;
    }
#pragma unroll
    for (int o = 8; o; o >>= 1) {
        a0 += __shfl_xor_sync(gmask, a0, o, 16);
        a1 += __shfl_xor_sync(gmask, a1, o, 16);
    }
    if (l == 0) {
        g_cnt[i] = 0;                      // restore invariant for next call
        float dii = g_dinv[i];
        float2 zi = g_z[i];
        float o0 = fmaf(a0 + zi.x, dii, b2[0]);
        float o1 = fmaf(a1 + zi.y, dii, b2[1]);
        float m   = fmaxf(o0, o1);
        float lse = m + log1pf(expf(fminf(o0, o1) - m));
        out[2 * i + 0] = o0 - lse;
        out[2 * i + 1] = o1 - lse;
    }
}

// ---------------- launch: fork GEMM after alloc, overlap fill ----------------
extern "C" void kernel_launch(void* const* d_in, const int* in_sizes, int n_in,
                              void* d_out, int out_size) {
    const float* x  = (const float*)d_in[0];
    const void*  ei = (const void*)d_in[1];
    const float* W1 = (const float*)d_in[2];
    const float* b1 = (const float*)d_in[3];
    const float* W2 = (const float*)d_in[4];
    const float* b2 = (const float*)d_in[5];
    float*       out = (float*)d_out;

    int N = in_sizes[0] / INF;
    int E = in_sizes[1] / 2;
    if (N > NMAX) N = NMAX;
    if (E > EMAX) E = EMAX;

    static cudaStream_t sG = (cudaStream_t)0;
    static cudaEvent_t  evA = (cudaEvent_t)0, evB = (cudaEvent_t)0;
    static int inited = 0;
    if (!inited) {
        if (cudaStreamCreateWithFlags(&sG, cudaStreamNonBlocking) != cudaSuccess) sG = 0;
        if (sG) {
            cudaEventCreateWithFlags(&evA, cudaEventDisableTiming);
            cudaEventCreateWithFlags(&evB, cudaEventDisableTiming);
        }
        inited = 1;
    }
    bool fork = (sG != 0);

    k_prep<<<(E / 4 + 255) / 256 + 1, 256>>>(ei, E);
    k_alloc<<<(N + 255) / 256, 256>>>(N);

    if (fork) {
        cudaEventRecord(evA, 0);                    // dinv ready
        cudaStreamWaitEvent(sG, evA, 0);
        k_gemm1<<<(N + 127) / 128, 128, 0, sG>>>(x, W1, N);  // overlaps k_fill
        cudaEventRecord(evB, sG);
    }

    k_fill<<<(E + 511) / 512, 512>>>(ei, E);

    if (fork) {
        cudaStreamWaitEvent(0, evB, 0);
    } else {
        k_gemm1<<<(N + 127) / 128, 128>>>(x, W1, N);
    }

    k_agg1<<<(N * 16 + 255) / 256, 256>>>(b1, W2, N);
    k_agg2<<<(N * 16 + 255) / 256, 256>>>(b2, out, N);
}

// round 16
// speedup vs baseline: 1.2415x; 1.2415x over previous
#include <cuda_runtime.h>
#include <cuda_fp16.h>
#include <cstdint>

#define NMAX  100000
#define EMAX  3200000
#define INF   128
#define HID   50
#define PITCH 64
#define SAP   72      // smem row stride in halfs (bank-conflict-free padding)

// ---------------- static device scratch (zero-initialized at load) -----------
__device__ int    g_is64;
__device__ int    g_cursor;        // reset to 0 at tail of k_agg2 each call
__device__ int    g_cnt[NMAX];     // reset to 0 at tail of k_agg2 each call
__device__ int2   g_oc[NMAX];      // (off, cnt)
__device__ int    g_wcur[NMAX];
__device__ int    g_csrc[EMAX];
__device__ float  g_dinv[NMAX];
__device__ __align__(128) __half g_h1h[(size_t)NMAX * PITCH]; // h1' = dinv*(x@W1)
__device__ float2 g_z[NMAX];                                  // z' = dinv*(h@W2)

// ---------------- dtype sniff (1 block, once) ----------------
__global__ void k_sniff(const unsigned int* __restrict__ p) {
    __shared__ int nz;
    int t = threadIdx.x;
    if (t == 0) nz = 0;
    __syncthreads();
    if (p[2 * t + 1] != 0u) atomicOr(&nz, 1);
    __syncthreads();
    if (t == 0) g_is64 = nz ? 0 : 1;
}

// ---------------- count degrees: int4, REDs are fire-and-forget --------------
__global__ void k_prep(const void* __restrict__ eiv, int E) {
    int i = (blockIdx.x * blockDim.x + threadIdx.x) * 4;
    if (i >= E) return;
    if (!g_is64 && i + 4 <= E) {
        int4 d = *(const int4*)((const int*)eiv + (size_t)E + i);
        atomicAdd(&g_cnt[d.x], 1);
        atomicAdd(&g_cnt[d.y], 1);
        atomicAdd(&g_cnt[d.z], 1);
        atomicAdd(&g_cnt[d.w], 1);
    } else {
        for (int j = i; j < E && j < i + 4; j++) {
            int d;
            if (g_is64) d = (int)((const long long*)eiv)[(size_t)E + j];
            else        d = ((const int*)eiv)[(size_t)E + j];
            atomicAdd(&g_cnt[d], 1);
        }
    }
}

// ---------------- region alloc: warp scan + one atomic per warp --------------
__global__ void k_alloc(int N) {
    int i = blockIdx.x * blockDim.x + threadIdx.x;
    int lane = threadIdx.x & 31;
    int c = (i < N) ? g_cnt[i] : 0;
    int x = c;
#pragma unroll
    for (int o = 1; o < 32; o <<= 1) {
        int y = __shfl_up_sync(0xffffffffu, x, o);
        if (lane >= o) x += y;
    }
    int total = __shfl_sync(0xffffffffu, x, 31);
    int base = 0;
    if (lane == 31 && total > 0) base = atomicAdd(&g_cursor, total);
    base = __shfl_sync(0xffffffffu, base, 31);
    if (i < N) {
        int off = base + x - c;
        g_oc[i]   = make_int2(off, c);
        g_wcur[i] = off;
        g_dinv[i] = rsqrtf((float)(c + 1));
    }
}

// ---------------- CSR fill (scalar: value-returning atomics) -----------------
__global__ void k_fill(const void* __restrict__ eiv, int E) {
    int i = blockIdx.x * blockDim.x + threadIdx.x;
    if (i >= E) return;
    int s, d;
    if (g_is64) {
        const long long* p = (const long long*)eiv;
        s = (int)p[i];
        d = (int)p[(size_t)E + i];
    } else {
        const int* p = (const int*)eiv;
        s = p[i];
        d = p[(size_t)E + i];
    }
    g_csrc[atomicAdd(&g_wcur[d], 1)] = s;
}

// ---------------- GEMM1 via mma.sync m16n8k16: h1' = dinv*(x @ W1) -----------
__global__ void k_gemm1(const float* __restrict__ x, const float* __restrict__ W1, int N) {
    __shared__ __half sA[128 * SAP];
    __shared__ __half sB[64 * SAP];
    int tid  = threadIdx.x;
    int lane = tid & 31;
    int wid  = tid >> 5;
    int node0 = blockIdx.x * 128;
    int r   = lane >> 2;
    int c2i = (lane & 3) * 2;

    float acc[2][8][4];
#pragma unroll
    for (int rg = 0; rg < 2; rg++)
#pragma unroll
        for (int cg = 0; cg < 8; cg++)
#pragma unroll
            for (int q = 0; q < 4; q++) acc[rg][cg][q] = 0.f;

    for (int kh = 0; kh < 2; kh++) {
        for (int idx = tid; idx < 1024; idx += 128) {
            int row = idx >> 3, ch = idx & 7;
            int node = node0 + row;
            float4 f0 = make_float4(0.f, 0.f, 0.f, 0.f), f1 = f0;
            if (node < N) {
                const float* src = x + (size_t)node * INF + kh * 64 + ch * 8;
                f0 = *(const float4*)src;
                f1 = *(const float4*)(src + 4);
            }
            __half2 h0 = __floats2half2_rn(f0.x, f0.y);
            __half2 h1 = __floats2half2_rn(f0.z, f0.w);
            __half2 h2 = __floats2half2_rn(f1.x, f1.y);
            __half2 h3 = __floats2half2_rn(f1.z, f1.w);
            uint4 v;
            v.x = *(uint32_t*)&h0; v.y = *(uint32_t*)&h1;
            v.z = *(uint32_t*)&h2; v.w = *(uint32_t*)&h3;
            *(uint4*)(sA + row * SAP + ch * 8) = v;
        }
        for (int idx = tid; idx < 4096; idx += 128) {
            int n = idx >> 6, k = idx & 63;
            sB[n * SAP + k] = (n < HID) ? __float2half(W1[(kh * 64 + k) * HID + n])
                                        : __half(0.f);
        }
        __syncthreads();
#pragma unroll
        for (int ks = 0; ks < 4; ks++) {
            int k = ks * 16;
            uint32_t b0[8], b1[8];
#pragma unroll
            for (int cg = 0; cg < 8; cg++) {
                const __half* bp = sB + (cg * 8 + r) * SAP + k + c2i;
                b0[cg] = *(const uint32_t*)bp;
                b1[cg] = *(const uint32_t*)(bp + 8);
            }
#pragma unroll
            for (int rg = 0; rg < 2; rg++) {
                const __half* ap = sA + (wid * 32 + rg * 16 + r) * SAP + k + c2i;
                uint32_t a0 = *(const uint32_t*)ap;
                uint32_t a1 = *(const uint32_t*)(ap + 8 * SAP);
                uint32_t a2 = *(const uint32_t*)(ap + 8);
                uint32_t a3 = *(const uint32_t*)(ap + 8 * SAP + 8);
#pragma unroll
                for (int cg = 0; cg < 8; cg++) {
                    asm volatile(
                        "mma.sync.aligned.m16n8k16.row.col.f32.f16.f16.f32 "
                        "{%0,%1,%2,%3}, {%4,%5,%6,%7}, {%8,%9}, {%0,%1,%2,%3};"
                        : "+f"(acc[rg][cg][0]), "+f"(acc[rg][cg][1]),
                          "+f"(acc[rg][cg][2]), "+f"(acc[rg][cg][3])
                        : "r"(a0), "r"(a1), "r"(a2), "r"(a3), "r"(b0[cg]), "r"(b1[cg]));
                }
            }
        }
        __syncthreads();
    }

#pragma unroll
    for (int rg = 0; rg < 2; rg++)
#pragma unroll
        for (int hr = 0; hr < 2; hr++) {
            int node = node0 + wid * 32 + rg * 16 + r + hr * 8;
            if (node < N) {
                float di = g_dinv[node];
                __half* dst = g_h1h + ((size_t)node << 6) + c2i;
#pragma unroll
                for (int cg = 0; cg < 8; cg++) {
                    __half2 hv = __floats2half2_rn(acc[rg][cg][hr * 2] * di,
                                                   acc[rg][cg][hr * 2 + 1] * di);
                    *(__half2*)(dst + cg * 8) = hv;
                }
            }
        }
}

// ---------------- layer-1 agg: 16-lane groups, 8-edge unroll -----------------
__global__ void k_agg1(const float* __restrict__ b1, const float* __restrict__ W2, int N) {
    int gt = blockIdx.x * blockDim.x + threadIdx.x;
    int i = gt >> 4;
    int l = gt & 15;
    if (i >= N) return;
    unsigned gmask = 0xFFFFu << (threadIdx.x & 16);

    float dii = g_dinv[i];
    int2 oc = g_oc[i];
    int beg = oc.x, end = beg + oc.y;

    bool act = l < 13;
    const __half* hbase = g_h1h;
    float a0 = 0.f, a1 = 0.f, a2 = 0.f, a3 = 0.f;
    if (act) {
        uint2 v = *(const uint2*)(hbase + ((size_t)i << 6) + l * 4);
        float2 f0 = __half22float2(*(__half2*)&v.x);
        float2 f1 = __half22float2(*(__half2*)&v.y);
        a0 = f0.x; a1 = f0.y; a2 = f1.x; a3 = f1.y;
    }
    int e = beg;
    int head = (4 - (beg & 3)) & 3;
    for (int j = 0; j < head && e < end; j++, e++) {
        int s = g_csrc[e];
        if (act) {
            uint2 v = *(const uint2*)(hbase + ((size_t)s << 6) + l * 4);
            float2 f0 = __half22float2(*(__half2*)&v.x);
            float2 f1 = __half22float2(*(__half2*)&v.y);
            a0 += f0.x; a1 += f0.y; a2 += f1.x; a3 += f1.y;
        }
    }
    for (; e + 8 <= end; e += 8) {
        int4 qa = *(const int4*)(g_csrc + e);
        int4 qb = *(const int4*)(g_csrc + e + 4);
        if (act) {
            uint2 v0 = *(const uint2*)(hbase + ((size_t)qa.x << 6) + l * 4);
            uint2 v1 = *(const uint2*)(hbase + ((size_t)qa.y << 6) + l * 4);
            uint2 v2 = *(const uint2*)(hbase + ((size_t)qa.z << 6) + l * 4);
            uint2 v3 = *(const uint2*)(hbase + ((size_t)qa.w << 6) + l * 4);
            uint2 v4 = *(const uint2*)(hbase + ((size_t)qb.x << 6) + l * 4);
            uint2 v5 = *(const uint2*)(hbase + ((size_t)qb.y << 6) + l * 4);
            uint2 v6 = *(const uint2*)(hbase + ((size_t)qb.z << 6) + l * 4);
            uint2 v7 = *(const uint2*)(hbase + ((size_t)qb.w << 6) + l * 4);
            float2 p0 = __half22float2(*(__half2*)&v0.x), p1 = __half22float2(*(__half2*)&v0.y);
            float2 p2 = __half22float2(*(__half2*)&v1.x), p3 = __half22float2(*(__half2*)&v1.y);
            float2 p4 = __half22float2(*(__half2*)&v2.x), p5 = __half22float2(*(__half2*)&v2.y);
            float2 p6 = __half22float2(*(__half2*)&v3.x), p7 = __half22float2(*(__half2*)&v3.y);
            float2 p8 = __half22float2(*(__half2*)&v4.x), p9 = __half22float2(*(__half2*)&v4.y);
            float2 pA = __half22float2(*(__half2*)&v5.x), pB = __half22float2(*(__half2*)&v5.y);
            float2 pC = __half22float2(*(__half2*)&v6.x), pD = __half22float2(*(__half2*)&v6.y);
            float2 pE = __half22float2(*(__half2*)&v7.x), pF = __half22float2(*(__half2*)&v7.y);
            a0 += ((p0.x + p2.x) + (p4.x + p6.x)) + ((p8.x + pA.x) + (pC.x + pE.x));
            a1 += ((p0.y + p2.y) + (p4.y + p6.y)) + ((p8.y + pA.y) + (pC.y + pE.y));
            a2 += ((p1.x + p3.x) + (p5.x + p7.x)) + ((p9.x + pB.x) + (pD.x + pF.x));
            a3 += ((p1.y + p3.y) + (p5.y + p7.y)) + ((p9.y + pB.y) + (pD.y + pF.y));
        }
    }
    for (; e + 4 <= end; e += 4) {
        int4 q = *(const int4*)(g_csrc + e);
        if (act) {
            uint2 v0 = *(const uint2*)(hbase + ((size_t)q.x << 6) + l * 4);
            uint2 v1 = *(const uint2*)(hbase + ((size_t)q.y << 6) + l * 4);
            uint2 v2 = *(const uint2*)(hbase + ((size_t)q.z << 6) + l * 4);
            uint2 v3 = *(const uint2*)(hbase + ((size_t)q.w << 6) + l * 4);
            float2 p0 = __half22float2(*(__half2*)&v0.x), p1 = __half22float2(*(__half2*)&v0.y);
            float2 p2 = __half22float2(*(__half2*)&v1.x), p3 = __half22float2(*(__half2*)&v1.y);
            float2 p4 = __half22float2(*(__half2*)&v2.x), p5 = __half22float2(*(__half2*)&v2.y);
            float2 p6 = __half22float2(*(__half2*)&v3.x), p7 = __half22float2(*(__half2*)&v3.y);
            a0 += (p0.x + p2.x) + (p4.x + p6.x);
            a1 += (p0.y + p2.y) + (p4.y + p6.y);
            a2 += (p1.x + p3.x) + (p5.x + p7.x);
            a3 += (p1.y + p3.y) + (p5.y + p7.y);
        }
    }
    for (; e < end; e++) {
        int s = g_csrc[e];
        if (act) {
            uint2 v = *(const uint2*)(hbase + ((size_t)s << 6) + l * 4);
            float2 f0 = __half22float2(*(__half2*)&v.x);
            float2 f1 = __half22float2(*(__half2*)&v.y);
            a0 += f0.x; a1 += f0.y; a2 += f1.x; a3 += f1.y;
        }
    }
    float z0 = 0.f, z1 = 0.f;
    if (l < 12) {
        float4 bb = *(const float4*)(b1 + 4 * l);
        float4 wA = *(const float4*)(W2 + 8 * l);
        float4 wB = *(const float4*)(W2 + 8 * l + 4);
        float h0 = fmaxf(fmaf(a0, dii, bb.x), 0.f);
        float h1 = fmaxf(fmaf(a1, dii, bb.y), 0.f);
        float h2 = fmaxf(fmaf(a2, dii, bb.z), 0.f);
        float h3 = fmaxf(fmaf(a3, dii, bb.w), 0.f);
        z0 = h0 * wA.x + h1 * wA.z + h2 * wB.x + h3 * wB.z;
        z1 = h0 * wA.y + h1 * wA.w + h2 * wB.y + h3 * wB.w;
    } else if (l == 12) {
        float2 bb = *(const float2*)(b1 + 48);
        float4 wA = *(const float4*)(W2 + 96);
        float h0 = fmaxf(fmaf(a0, dii, bb.x), 0.f);
        float h1 = fmaxf(fmaf(a1, dii, bb.y), 0.f);
        z0 = h0 * wA.x + h1 * wA.z;
        z1 = h0 * wA.y + h1 * wA.w;
    }
#pragma unroll
    for (int o = 8; o; o >>= 1) {
        z0 += __shfl_xor_sync(gmask, z0, o, 16);
        z1 += __shfl_xor_sync(gmask, z1, o, 16);
    }
    if (l == 0) g_z[i] = make_float2(z0 * dii, z1 * dii);
}

// ---------------- layer-2 agg + log_softmax (16-lane groups) -----------------
__global__ void k_agg2(const float* __restrict__ b2, float* __restrict__ out, int N) {
    int gt = blockIdx.x * blockDim.x + threadIdx.x;
    int i = gt >> 4, l = gt & 15;
    if (gt == 0) g_cursor = 0;
    if (i >= N) return;
    unsigned gmask = 0xFFFFu << (threadIdx.x & 16);

    int2 oc = g_oc[i];
    int beg = oc.x;
    int end = beg + oc.y;
    float a0 = 0.f, a1 = 0.f;
    for (int e = beg + l; e < end; e += 16) {
        float2 zv = g_z[g_csrc[e]];
        a0 += zv.x;
        a1 += zv.y;
    }
#pragma unroll
    for (int o = 8; o; o >>= 1) {
        a0 += __shfl_xor_sync(gmask, a0, o, 16);
        a1 += __shfl_xor_sync(gmask, a1, o, 16);
    }
    if (l == 0) {
        g_cnt[i] = 0;                      // restore invariant for next call
        float dii = g_dinv[i];
        float2 zi = g_z[i];
        float o0 = fmaf(a0 + zi.x, dii, b2[0]);
        float o1 = fmaf(a1 + zi.y, dii, b2[1]);
        float m   = fmaxf(o0, o1);
        float lse = m + log1pf(expf(fminf(o0, o1) - m));
        out[2 * i + 0] = o0 - lse;
        out[2 * i + 1] = o1 - lse;
    }
}

// ---------------- launch: fork GEMM after alloc, overlap fill ----------------
extern "C" void kernel_launch(void* const* d_in, const int* in_sizes, int n_in,
                              void* d_out, int out_size) {
    const float* x  = (const float*)d_in[0];
    const void*  ei = (const void*)d_in[1];
    const float* W1 = (const float*)d_in[2];
    const float* b1 = (const float*)d_in[3];
    const float* W2 = (const float*)d_in[4];
    const float* b2 = (const float*)d_in[5];
    float*       out = (float*)d_out;

    int N = in_sizes[0] / INF;
    int E = in_sizes[1] / 2;
    if (N > NMAX) N = NMAX;
    if (E > EMAX) E = EMAX;

    static cudaStream_t sG = (cudaStream_t)0;
    static cudaEvent_t  evA = (cudaEvent_t)0, evB = (cudaEvent_t)0;
    static int inited = 0;
    if (!inited) {
        if (cudaStreamCreateWithFlags(&sG, cudaStreamNonBlocking) != cudaSuccess) sG = 0;
        if (sG) {
            cudaEventCreateWithFlags(&evA, cudaEventDisableTiming);
            cudaEventCreateWithFlags(&evB, cudaEventDisableTiming);
        }
        inited = 1;
    }
    bool fork = (sG != 0);

    k_sniff<<<1, 256>>>((const unsigned int*)ei);
    k_prep<<<(E / 4 + 255) / 256 + 1, 256>>>(ei, E);
    k_alloc<<<(N + 255) / 256, 256>>>(N);

    if (fork) {
        cudaEventRecord(evA, 0);                    // dinv ready
        cudaStreamWaitEvent(sG, evA, 0);
        k_gemm1<<<(N + 127) / 128, 128, 0, sG>>>(x, W1, N);  // overlaps k_fill
        cudaEventRecord(evB, sG);
    }

    k_fill<<<(E + 255) / 256, 256>>>(ei, E);

    if (fork) {
        cudaStreamWaitEvent(0, evB, 0);
    } else {
        k_gemm1<<<(N + 127) / 128, 128>>>(x, W1, N);
    }

    k_agg1<<<(N * 16 + 255) / 256, 256>>>(b1, W2, N);
    k_agg2<<<(N * 16 + 255) / 256, 256>>>(b2, out, N);
}